// round 4
// baseline (speedup 1.0000x reference)
#include <cuda_runtime.h>
#include <math.h>
#include <stdint.h>

#define NTOK   8192
#define DM     1024
#define NH     4
#define DQ     256
#define NSUB   128
#define TK     8
#define DL     256
#define DH     512
#define NEXP   16384
#define BN_EPS 1e-5f

// ---------------- scratch (static __device__: allocation-free) ----------------
__device__ float g_q[NTOK * 1024];          // 32 MB
__device__ float g_sum[1024];
__device__ float g_sqs[1024];
__device__ float g_a[1024];
__device__ float g_b[1024];
__device__ float g_sk1a[NH * 128 * 128];
__device__ float g_sk2a[NH * 128 * 128];
__device__ float g_bs1[NH * 128];
__device__ float g_bs2[NH * 128];
__device__ float g_s1[NTOK * NH * 128];     // 16 MB
__device__ float g_s2[NTOK * NH * 128];     // 16 MB
__device__ float g_probs[NTOK * NH * TK];
__device__ int   g_eidx[NTOK * NH * TK];
__device__ float g_H[NEXP * DH];            // 32 MB
__device__ float g_xp[NTOK * DH];           // 16 MB
__device__ float g_acc[NTOK * DH];          // 16 MB

__device__ __forceinline__ float gelu_exact(float x) {
    return 0.5f * x * (1.0f + erff(x * 0.70710678118654752440f));
}

// ---------------- tiny utility kernels ----------------
__global__ void zero_stats_kernel() {
    int i = threadIdx.x;
    g_sum[i] = 0.0f;
    g_sqs[i] = 0.0f;
}

// BatchNorm statistics over rows of g_q (8192 x 1024)
__global__ void bn_reduce_kernel() {
    int tid = threadIdx.x;             // 256
    int r0 = blockIdx.x * 64;          // 128 blocks
    float s0 = 0.f, s1 = 0.f, s2 = 0.f, s3 = 0.f;
    float q0 = 0.f, q1 = 0.f, q2 = 0.f, q3 = 0.f;
    for (int r = 0; r < 64; r++) {
        const float* row = g_q + (size_t)(r0 + r) * 1024;
        float v0 = row[tid];
        float v1 = row[tid + 256];
        float v2 = row[tid + 512];
        float v3 = row[tid + 768];
        s0 += v0; q0 += v0 * v0;
        s1 += v1; q1 += v1 * v1;
        s2 += v2; q2 += v2 * v2;
        s3 += v3; q3 += v3 * v3;
    }
    atomicAdd(&g_sum[tid],       s0);
    atomicAdd(&g_sum[tid + 256], s1);
    atomicAdd(&g_sum[tid + 512], s2);
    atomicAdd(&g_sum[tid + 768], s3);
    atomicAdd(&g_sqs[tid],       q0);
    atomicAdd(&g_sqs[tid + 256], q1);
    atomicAdd(&g_sqs[tid + 512], q2);
    atomicAdd(&g_sqs[tid + 768], q3);
}

__global__ void bn_finalize_kernel(const float* __restrict__ gamma,
                                   const float* __restrict__ beta) {
    int c = threadIdx.x;  // 1024
    float mean = g_sum[c] * (1.0f / NTOK);
    float var  = g_sqs[c] * (1.0f / NTOK) - mean * mean;
    float rstd = rsqrtf(var + BN_EPS);
    float a = gamma[c] * rstd;
    g_a[c] = a;
    g_b[c] = beta[c] - mean * a;
}

// Fold the BN affine into the score projection weights:
// s1[n,h,k] = sum_j (q[n,h*256+j]*a + b) * sk1[k,j]  ==  q @ (sk1*a)^T + (b @ sk1^T)
__global__ void fold_sk_kernel(const float* __restrict__ sk1,
                               const float* __restrict__ sk2) {
    int h = blockIdx.x >> 7;      // 512 blocks
    int k = blockIdx.x & 127;
    int j = threadIdx.x;          // 128
    float w1 = sk1[k * 128 + j];
    float w2 = sk2[k * 128 + j];
    float a1 = g_a[h * 256 + j],       b1 = g_b[h * 256 + j];
    float a2 = g_a[h * 256 + 128 + j], b2 = g_b[h * 256 + 128 + j];
    g_sk1a[(h * 128 + k) * 128 + j] = w1 * a1;
    g_sk2a[(h * 128 + k) * 128 + j] = w2 * a2;
    float p1 = w1 * b1, p2 = w2 * b2;
    // block reduce 128 threads
    const unsigned FULL = 0xffffffffu;
    #pragma unroll
    for (int off = 16; off > 0; off >>= 1) {
        p1 += __shfl_down_sync(FULL, p1, off);
        p2 += __shfl_down_sync(FULL, p2, off);
    }
    __shared__ float sh[8];
    int w = j >> 5, l = j & 31;
    if (l == 0) { sh[w] = p1; sh[4 + w] = p2; }
    __syncthreads();
    if (j == 0) {
        g_bs1[h * 128 + k] = sh[0] + sh[1] + sh[2] + sh[3];
        g_bs2[h * 128 + k] = sh[4] + sh[5] + sh[6] + sh[7];
    }
}

// ---------------- generic tiled fp32 GEMM ----------------
// C[M,N] = A[M,K] * op(B) (+bias per col) (gelu) (* scale)
// transB=1: B is [N,K] row-major. transB=0: B is [K,N] row-major.
// Grid: x = N/64, y = M/64, z = batch (aS/bS/cS/biasS element offsets per z).
__global__ void __launch_bounds__(256)
sgemm64(const float* __restrict__ A, const float* __restrict__ B,
        float* __restrict__ C, const float* __restrict__ bias,
        int K, int lda, int ldb, int ldc,
        long long aS, long long bS, long long cS, long long biasS,
        int transB, int epi, float scale) {
    A += (long long)blockIdx.z * aS;
    B += (long long)blockIdx.z * bS;
    C += (long long)blockIdx.z * cS;
    const float* biasz = bias ? (bias + (long long)blockIdx.z * biasS) : nullptr;

    __shared__ __align__(16) float As[16][64];
    __shared__ __align__(16) float Bs[16][64];

    int tid = threadIdx.x;
    int m0 = blockIdx.y * 64, n0 = blockIdx.x * 64;
    int tx = tid & 15, ty = tid >> 4;

    float acc[4][4];
    #pragma unroll
    for (int i = 0; i < 4; i++)
        #pragma unroll
        for (int j = 0; j < 4; j++) acc[i][j] = 0.0f;

    int ra = tid >> 2, ka = (tid & 3) * 4;     // A / transB loads
    int kb = tid >> 4, nb = (tid & 15) * 4;    // non-trans B loads

    for (int k0 = 0; k0 < K; k0 += 16) {
        float4 av = *(const float4*)(A + (long long)(m0 + ra) * lda + k0 + ka);
        As[ka][ra] = av.x; As[ka + 1][ra] = av.y;
        As[ka + 2][ra] = av.z; As[ka + 3][ra] = av.w;
        if (transB) {
            float4 bv = *(const float4*)(B + (long long)(n0 + ra) * ldb + k0 + ka);
            Bs[ka][ra] = bv.x; Bs[ka + 1][ra] = bv.y;
            Bs[ka + 2][ra] = bv.z; Bs[ka + 3][ra] = bv.w;
        } else {
            float4 bv = *(const float4*)(B + (long long)(k0 + kb) * ldb + n0 + nb);
            *(float4*)&Bs[kb][nb] = bv;
        }
        __syncthreads();
        #pragma unroll
        for (int kk = 0; kk < 16; kk++) {
            float4 a4 = *(const float4*)&As[kk][ty * 4];
            float4 b4 = *(const float4*)&Bs[kk][tx * 4];
            float a[4] = {a4.x, a4.y, a4.z, a4.w};
            float b[4] = {b4.x, b4.y, b4.z, b4.w};
            #pragma unroll
            for (int i = 0; i < 4; i++)
                #pragma unroll
                for (int j = 0; j < 4; j++)
                    acc[i][j] = fmaf(a[i], b[j], acc[i][j]);
        }
        __syncthreads();
    }

    #pragma unroll
    for (int i = 0; i < 4; i++) {
        long long row = m0 + ty * 4 + i;
        #pragma unroll
        for (int j = 0; j < 4; j++) {
            int col = n0 + tx * 4 + j;
            float v = acc[i][j];
            if (epi == 1) v += biasz[col];
            else if (epi == 2) v = gelu_exact(v);
            v *= scale;
            C[row * ldc + col] = v;
        }
    }
}

// ---------------- top-k machinery: one warp per (n,h) ----------------
__global__ void __launch_bounds__(256) topk_kernel() {
    const unsigned FULL = 0xffffffffu;
    int gw = (blockIdx.x * 256 + threadIdx.x) >> 5;   // 0..32767
    int lane = threadIdx.x & 31;
    const float* p1 = g_s1 + (size_t)gw * 128;
    const float* p2 = g_s2 + (size_t)gw * 128;

    float v1[4], v2[4];
    #pragma unroll
    for (int i = 0; i < 4; i++) {
        v1[i] = p1[lane + 32 * i];
        v2[i] = p2[lane + 32 * i];
    }

    // top-16 of each score set; slot t kept in lane t's registers
    float slot_v1 = 0.f, slot_v2 = 0.f;
    int   slot_i1 = 0,   slot_i2 = 0;
    #pragma unroll
    for (int t = 0; t < 16; t++) {
        // --- s1 ---
        {
            float bv = v1[0]; int bi = lane;
            #pragma unroll
            for (int i = 1; i < 4; i++)
                if (v1[i] > bv) { bv = v1[i]; bi = lane + 32 * i; }
            #pragma unroll
            for (int off = 16; off > 0; off >>= 1) {
                float ov = __shfl_down_sync(FULL, bv, off);
                int   oi = __shfl_down_sync(FULL, bi, off);
                if (ov > bv || (ov == bv && oi < bi)) { bv = ov; bi = oi; }
            }
            bv = __shfl_sync(FULL, bv, 0);
            bi = __shfl_sync(FULL, bi, 0);
            if (lane == t) { slot_v1 = bv; slot_i1 = bi; }
            int sl = bi >> 5, ol = bi & 31;
            if (lane == ol) {
                if      (sl == 0) v1[0] = -3.4e38f;
                else if (sl == 1) v1[1] = -3.4e38f;
                else if (sl == 2) v1[2] = -3.4e38f;
                else              v1[3] = -3.4e38f;
            }
        }
        // --- s2 ---
        {
            float bv = v2[0]; int bi = lane;
            #pragma unroll
            for (int i = 1; i < 4; i++)
                if (v2[i] > bv) { bv = v2[i]; bi = lane + 32 * i; }
            #pragma unroll
            for (int off = 16; off > 0; off >>= 1) {
                float ov = __shfl_down_sync(FULL, bv, off);
                int   oi = __shfl_down_sync(FULL, bi, off);
                if (ov > bv || (ov == bv && oi < bi)) { bv = ov; bi = oi; }
            }
            bv = __shfl_sync(FULL, bv, 0);
            bi = __shfl_sync(FULL, bi, 0);
            if (lane == t) { slot_v2 = bv; slot_i2 = bi; }
            int sl = bi >> 5, ol = bi & 31;
            if (lane == ol) {
                if      (sl == 0) v2[0] = -3.4e38f;
                else if (sl == 1) v2[1] = -3.4e38f;
                else if (sl == 2) v2[2] = -3.4e38f;
                else              v2[3] = -3.4e38f;
            }
        }
    }

    // 256 combos: c = lane + 32*j; value = top1[c>>4] + top2[c&15]
    float cv[8];
    #pragma unroll
    for (int j = 0; j < 8; j++) {
        int c = lane + 32 * j;
        float a = __shfl_sync(FULL, slot_v1, c >> 4);
        float b = __shfl_sync(FULL, slot_v2, c & 15);
        cv[j] = a + b;
    }

    float sel_v = -3.4e38f; int sel_c = 0;
    #pragma unroll
    for (int t = 0; t < 8; t++) {
        float bv = cv[0]; int bc = lane;
        #pragma unroll
        for (int j = 1; j < 8; j++)
            if (cv[j] > bv) { bv = cv[j]; bc = lane + 32 * j; }
        #pragma unroll
        for (int off = 16; off > 0; off >>= 1) {
            float ov = __shfl_down_sync(FULL, bv, off);
            int   oc = __shfl_down_sync(FULL, bc, off);
            if (ov > bv || (ov == bv && oc < bc)) { bv = ov; bc = oc; }
        }
        bv = __shfl_sync(FULL, bv, 0);
        bc = __shfl_sync(FULL, bc, 0);
        if (lane == t) { sel_v = bv; sel_c = bc; }
        int sl = bc >> 5, ol = bc & 31;
        if (lane == ol) {
            switch (sl) {
                case 0: cv[0] = -3.4e38f; break;
                case 1: cv[1] = -3.4e38f; break;
                case 2: cv[2] = -3.4e38f; break;
                case 3: cv[3] = -3.4e38f; break;
                case 4: cv[4] = -3.4e38f; break;
                case 5: cv[5] = -3.4e38f; break;
                case 6: cv[6] = -3.4e38f; break;
                default: cv[7] = -3.4e38f; break;
            }
        }
    }

    // softmax over the 8 selected (lanes 0..7 hold them)
    float mv = (lane < 8) ? sel_v : -3.4e38f;
    #pragma unroll
    for (int off = 4; off > 0; off >>= 1)
        mv = fmaxf(mv, __shfl_xor_sync(FULL, mv, off));
    float ev = (lane < 8) ? expf(sel_v - mv) : 0.0f;
    float sum = ev;
    #pragma unroll
    for (int off = 4; off > 0; off >>= 1)
        sum += __shfl_xor_sync(FULL, sum, off);
    float p = ev / sum;

    int i1 = __shfl_sync(FULL, slot_i1, sel_c >> 4);
    int i2 = __shfl_sync(FULL, slot_i2, sel_c & 15);
    if (lane < 8) {
        g_probs[(size_t)gw * 8 + lane] = p;
        g_eidx [(size_t)gw * 8 + lane] = i1 * NSUB + i2;
    }
}

// ---------------- expert gather + dot + gelu + weighted accumulate ----------------
// One block (256 threads, 8 warps) per token. H_all is 32MB -> L2-resident.
__global__ void __launch_bounds__(256) gather_kernel() {
    const unsigned FULL = 0xffffffffu;
    __shared__ float sx[DH];
    __shared__ float sacc[8][DH];   // per-warp partial accumulators
    int n = blockIdx.x;
    int tid = threadIdx.x;
    int w = tid >> 5, lane = tid & 31;

    sx[tid]       = g_xp[(size_t)n * DH + tid];
    sx[tid + 256] = g_xp[(size_t)n * DH + tid + 256];
    #pragma unroll
    for (int i = 0; i < 16; i++) sacc[w][lane + 32 * i] = 0.0f;
    __syncthreads();

    #pragma unroll
    for (int p = 0; p < 4; p++) {
        int idx = w * 4 + p;                  // covers the 32 (h,k) pairs
        int e = g_eidx[(size_t)n * 32 + idx];
        float prob = g_probs[(size_t)n * 32 + idx];
        const float* hrow = g_H + (size_t)e * DH;
        float hv[16];
        float dot = 0.0f;
        #pragma unroll
        for (int i = 0; i < 16; i++) {
            hv[i] = hrow[lane + 32 * i];
            dot = fmaf(hv[i], sx[lane + 32 * i], dot);
        }
        #pragma unroll
        for (int off = 16; off > 0; off >>= 1)
            dot += __shfl_down_sync(FULL, dot, off);
        dot = __shfl_sync(FULL, dot, 0);
        float act = gelu_exact(dot) * prob;
        #pragma unroll
        for (int i = 0; i < 16; i++)
            sacc[w][lane + 32 * i] = fmaf(act, hv[i], sacc[w][lane + 32 * i]);
    }
    __syncthreads();

    // reduce 8 warp partials -> g_acc
    for (int c = tid; c < DH; c += 256) {
        float s = 0.0f;
        #pragma unroll
        for (int ww = 0; ww < 8; ww++) s += sacc[ww][c];
        g_acc[(size_t)n * DH + c] = s;
    }
}

// ---------------- host launcher ----------------
extern "C" void kernel_launch(void* const* d_in, const int* in_sizes, int n_in,
                              void* d_out, int out_size) {
    (void)in_sizes; (void)n_in; (void)out_size;
    const float* x    = (const float*)d_in[0];
    const float* Wq   = (const float*)d_in[1];
    const float* bq   = (const float*)d_in[2];
    const float* gam  = (const float*)d_in[3];
    const float* bet  = (const float*)d_in[4];
    const float* sk1  = (const float*)d_in[5];
    const float* sk2  = (const float*)d_in[6];
    const float* lat  = (const float*)d_in[7];
    const float* W1   = (const float*)d_in[8];
    const float* W2   = (const float*)d_in[9];
    float* out = (float*)d_out;

    float *q, *sk1a, *sk2a, *bs1, *bs2, *s1, *s2, *H, *xp, *acc;
    cudaGetSymbolAddress((void**)&q,    g_q);
    cudaGetSymbolAddress((void**)&sk1a, g_sk1a);
    cudaGetSymbolAddress((void**)&sk2a, g_sk2a);
    cudaGetSymbolAddress((void**)&bs1,  g_bs1);
    cudaGetSymbolAddress((void**)&bs2,  g_bs2);
    cudaGetSymbolAddress((void**)&s1,   g_s1);
    cudaGetSymbolAddress((void**)&s2,   g_s2);
    cudaGetSymbolAddress((void**)&H,    g_H);
    cudaGetSymbolAddress((void**)&xp,   g_xp);
    cudaGetSymbolAddress((void**)&acc,  g_acc);

    // 1. zero BN accumulators
    zero_stats_kernel<<<1, 1024>>>();

    // 2. q = x @ Wq^T + bq   [8192,1024] x [1024,1024]^T
    sgemm64<<<dim3(16, 128), 256>>>(x, Wq, q, bq,
                                    1024, 1024, 1024, 1024,
                                    0, 0, 0, 0, 1, 1, 1.0f);

    // 3-5. BN stats, fold into affine, fold affine into score weights
    bn_reduce_kernel<<<128, 256>>>();
    bn_finalize_kernel<<<1, 1024>>>(gam, bet);
    fold_sk_kernel<<<512, 128>>>(sk1, sk2);

    // 6-7. s1, s2 = q_half @ (sk*a)^T + bias  (batched over heads via z)
    sgemm64<<<dim3(2, 128, 4), 256>>>(q, sk1a, s1, bs1,
                                      128, 1024, 128, 512,
                                      256, 128 * 128, 128, 128, 1, 1, 1.0f);
    sgemm64<<<dim3(2, 128, 4), 256>>>(q + 128, sk2a, s2, bs2,
                                      128, 1024, 128, 512,
                                      256, 128 * 128, 128, 128, 1, 1, 1.0f);

    // 8. top-16 x top-16 -> top-8, softmax, expert indices
    topk_kernel<<<4096, 256>>>();

    // 9. H = gelu(latents @ W1)   [16384,256] x [256,512]
    sgemm64<<<dim3(8, 256), 256>>>(lat, W1, H, nullptr,
                                   256, 256, 512, 512,
                                   0, 0, 0, 0, 0, 2, 1.0f);

    // 10. x_proj = x @ W2[:, :1024]^T   [8192,1024] x [512,1024(ld2048)]^T
    sgemm64<<<dim3(8, 128), 256>>>(x, W2, xp, nullptr,
                                   1024, 1024, 2048, 512,
                                   0, 0, 0, 0, 1, 0, 1.0f);

    // 11. gather experts, act = gelu(<hg, x_proj>)*prob, acc = sum act*hg
    gather_kernel<<<NTOK, 256>>>();

    // 12. out = acc @ Wv / NUM_HEADS   [8192,512] x [512,1024(ld2048)]
    sgemm64<<<dim3(16, 128), 256>>>(acc, W2 + 1024, out, nullptr,
                                    512, 512, 2048, 1024,
                                    0, 0, 0, 0, 0, 0, 0.25f);
}

// round 5
// speedup vs baseline: 1.3451x; 1.3451x over previous
#include <cuda_runtime.h>
#include <math.h>
#include <stdint.h>

#define NTOK   8192
#define DM     1024
#define NH     4
#define DQ     256
#define NSUB   128
#define TK     8
#define DL     256
#define DH     512
#define NEXP   16384
#define BN_EPS 1e-5f

// ---------------- scratch (static __device__: allocation-free) ----------------
__device__ float g_q[NTOK * 1024];          // 32 MB
__device__ float g_sum[1024];
__device__ float g_sqs[1024];
__device__ float g_a[1024];
__device__ float g_b[1024];
__device__ float g_sk1a[NH * 128 * 128];
__device__ float g_sk2a[NH * 128 * 128];
__device__ float g_bs1[NH * 128];
__device__ float g_bs2[NH * 128];
__device__ float g_s1[NTOK * NH * 128];     // 16 MB
__device__ float g_s2[NTOK * NH * 128];     // 16 MB
__device__ float g_probs[NTOK * NH * TK];
__device__ int   g_eidx[NTOK * NH * TK];
__device__ float g_H[NEXP * DH];            // 32 MB
__device__ float g_xp[NTOK * DH];           // 16 MB
__device__ float g_acc[NTOK * DH];          // 16 MB

__device__ __forceinline__ float gelu_exact(float x) {
    return 0.5f * x * (1.0f + erff(x * 0.70710678118654752440f));
}

// ---------------- tiny utility kernels ----------------
__global__ void zero_stats_kernel() {
    int i = threadIdx.x;
    g_sum[i] = 0.0f;
    g_sqs[i] = 0.0f;
}

// BatchNorm statistics over rows of g_q (8192 x 1024)
__global__ void bn_reduce_kernel() {
    int tid = threadIdx.x;             // 256
    int r0 = blockIdx.x * 64;          // 128 blocks
    float s0 = 0.f, s1 = 0.f, s2 = 0.f, s3 = 0.f;
    float q0 = 0.f, q1 = 0.f, q2 = 0.f, q3 = 0.f;
    for (int r = 0; r < 64; r++) {
        const float* row = g_q + (size_t)(r0 + r) * 1024;
        float v0 = row[tid];
        float v1 = row[tid + 256];
        float v2 = row[tid + 512];
        float v3 = row[tid + 768];
        s0 += v0; q0 += v0 * v0;
        s1 += v1; q1 += v1 * v1;
        s2 += v2; q2 += v2 * v2;
        s3 += v3; q3 += v3 * v3;
    }
    atomicAdd(&g_sum[tid],       s0);
    atomicAdd(&g_sum[tid + 256], s1);
    atomicAdd(&g_sum[tid + 512], s2);
    atomicAdd(&g_sum[tid + 768], s3);
    atomicAdd(&g_sqs[tid],       q0);
    atomicAdd(&g_sqs[tid + 256], q1);
    atomicAdd(&g_sqs[tid + 512], q2);
    atomicAdd(&g_sqs[tid + 768], q3);
}

__global__ void bn_finalize_kernel(const float* __restrict__ gamma,
                                   const float* __restrict__ beta) {
    int c = threadIdx.x;  // 1024
    float mean = g_sum[c] * (1.0f / NTOK);
    float var  = g_sqs[c] * (1.0f / NTOK) - mean * mean;
    float rstd = rsqrtf(var + BN_EPS);
    float a = gamma[c] * rstd;
    g_a[c] = a;
    g_b[c] = beta[c] - mean * a;
}

// Fold the BN affine into the score projection weights:
// s1[n,h,k] = sum_j (q[n,h*256+j]*a + b) * sk1[k,j]  ==  q @ (sk1*a)^T + (b @ sk1^T)
__global__ void fold_sk_kernel(const float* __restrict__ sk1,
                               const float* __restrict__ sk2) {
    int h = blockIdx.x >> 7;      // 512 blocks
    int k = blockIdx.x & 127;
    int j = threadIdx.x;          // 128
    float w1 = sk1[k * 128 + j];
    float w2 = sk2[k * 128 + j];
    float a1 = g_a[h * 256 + j],       b1 = g_b[h * 256 + j];
    float a2 = g_a[h * 256 + 128 + j], b2 = g_b[h * 256 + 128 + j];
    g_sk1a[(h * 128 + k) * 128 + j] = w1 * a1;
    g_sk2a[(h * 128 + k) * 128 + j] = w2 * a2;
    float p1 = w1 * b1, p2 = w2 * b2;
    const unsigned FULL = 0xffffffffu;
    #pragma unroll
    for (int off = 16; off > 0; off >>= 1) {
        p1 += __shfl_down_sync(FULL, p1, off);
        p2 += __shfl_down_sync(FULL, p2, off);
    }
    __shared__ float sh[8];
    int w = j >> 5, l = j & 31;
    if (l == 0) { sh[w] = p1; sh[4 + w] = p2; }
    __syncthreads();
    if (j == 0) {
        g_bs1[h * 128 + k] = sh[0] + sh[1] + sh[2] + sh[3];
        g_bs2[h * 128 + k] = sh[4] + sh[5] + sh[6] + sh[7];
    }
}

// ---------------- high-throughput tiled fp32 GEMM ----------------
// 128x128 block tile, 8x8 micro-tile per thread, K-tile = 8, double-buffered SMEM.
// C[M,N] = A[M,K] * op(B) (+bias per col | gelu) * scale
// transB=1: B is [N,K] row-major. transB=0: B is [K,N] row-major.
// Grid: x = N/128, y = M/128, z = batch (aS/bS/cS/biasS element offsets per z).
// Requires: M%128==0, N%128==0, K%8==0, 16B-aligned pointers/ld.
__global__ void __launch_bounds__(256)
sgemm128(const float* __restrict__ A, const float* __restrict__ B,
         float* __restrict__ C, const float* __restrict__ bias,
         int K, int lda, int ldb, int ldc,
         long long aS, long long bS, long long cS, long long biasS,
         int transB, int epi, float scale) {
    A += (long long)blockIdx.z * aS;
    B += (long long)blockIdx.z * bS;
    C += (long long)blockIdx.z * cS;
    const float* biasz = bias ? (bias + (long long)blockIdx.z * biasS) : nullptr;

    __shared__ __align__(16) float As[2][8][128];
    __shared__ __align__(16) float Bs[2][8][128];

    int tid = threadIdx.x;
    int m0 = blockIdx.y * 128, n0 = blockIdx.x * 128;
    int tx = tid & 15, ty = tid >> 4;

    float acc[8][8];
    #pragma unroll
    for (int i = 0; i < 8; i++)
        #pragma unroll
        for (int j = 0; j < 8; j++) acc[i][j] = 0.0f;

    // global-load mapping
    int hr = tid >> 1, hk = (tid & 1) * 4;     // A rows / transB rows
    int br = tid >> 5, bc = (tid & 31) * 4;    // non-trans B

    const float* Aptr = A + (long long)(m0 + hr) * lda + hk;
    const float* Bptr;
    long long bstep;
    if (transB) { Bptr = B + (long long)(n0 + hr) * ldb + hk; bstep = 8; }
    else        { Bptr = B + (long long)br * ldb + n0 + bc;   bstep = 8LL * ldb; }

    // prefetch tile 0
    float4 av = *(const float4*)Aptr;
    float4 bv = *(const float4*)Bptr;
    As[0][hk + 0][hr] = av.x; As[0][hk + 1][hr] = av.y;
    As[0][hk + 2][hr] = av.z; As[0][hk + 3][hr] = av.w;
    if (transB) {
        Bs[0][hk + 0][hr] = bv.x; Bs[0][hk + 1][hr] = bv.y;
        Bs[0][hk + 2][hr] = bv.z; Bs[0][hk + 3][hr] = bv.w;
    } else {
        *(float4*)&Bs[0][br][bc] = bv;
    }
    __syncthreads();

    int nk = K >> 3;
    for (int kt = 0; kt < nk; kt++) {
        int cur = kt & 1;
        bool more = (kt + 1 < nk);
        if (more) {
            av = *(const float4*)(Aptr + (long long)(kt + 1) * 8);
            bv = *(const float4*)(Bptr + (long long)(kt + 1) * bstep);
        }
        #pragma unroll
        for (int kk = 0; kk < 8; kk++) {
            float4 a0 = *(const float4*)&As[cur][kk][ty * 4];
            float4 a1 = *(const float4*)&As[cur][kk][ty * 4 + 64];
            float4 b0 = *(const float4*)&Bs[cur][kk][tx * 4];
            float4 b1 = *(const float4*)&Bs[cur][kk][tx * 4 + 64];
            float a[8] = {a0.x, a0.y, a0.z, a0.w, a1.x, a1.y, a1.z, a1.w};
            float b[8] = {b0.x, b0.y, b0.z, b0.w, b1.x, b1.y, b1.z, b1.w};
            #pragma unroll
            for (int i = 0; i < 8; i++)
                #pragma unroll
                for (int j = 0; j < 8; j++)
                    acc[i][j] = fmaf(a[i], b[j], acc[i][j]);
        }
        if (more) {
            int nxt = cur ^ 1;
            As[nxt][hk + 0][hr] = av.x; As[nxt][hk + 1][hr] = av.y;
            As[nxt][hk + 2][hr] = av.z; As[nxt][hk + 3][hr] = av.w;
            if (transB) {
                Bs[nxt][hk + 0][hr] = bv.x; Bs[nxt][hk + 1][hr] = bv.y;
                Bs[nxt][hk + 2][hr] = bv.z; Bs[nxt][hk + 3][hr] = bv.w;
            } else {
                *(float4*)&Bs[nxt][br][bc] = bv;
            }
            __syncthreads();
        }
    }

    // epilogue: rows ty*4 + {0..3, 64..67}, cols tx*4 + {0..3, 64..67}
    #pragma unroll
    for (int i = 0; i < 8; i++) {
        long long row = m0 + ty * 4 + (i & 3) + (i >> 2) * 64;
        #pragma unroll
        for (int jh = 0; jh < 2; jh++) {
            int col = n0 + tx * 4 + jh * 64;
            float4 v;
            float* vp = &v.x;
            #pragma unroll
            for (int j = 0; j < 4; j++) {
                float t = acc[i][jh * 4 + j];
                if (epi == 1) t += biasz[col + j];
                else if (epi == 2) t = gelu_exact(t);
                vp[j] = t * scale;
            }
            *(float4*)(C + row * ldc + col) = v;
        }
    }
}

// ---------------- top-k machinery: one warp per (n,h) ----------------
__global__ void __launch_bounds__(256) topk_kernel() {
    const unsigned FULL = 0xffffffffu;
    int gw = (blockIdx.x * 256 + threadIdx.x) >> 5;   // 0..32767
    int lane = threadIdx.x & 31;
    const float* p1 = g_s1 + (size_t)gw * 128;
    const float* p2 = g_s2 + (size_t)gw * 128;

    float v1[4], v2[4];
    #pragma unroll
    for (int i = 0; i < 4; i++) {
        v1[i] = p1[lane + 32 * i];
        v2[i] = p2[lane + 32 * i];
    }

    float slot_v1 = 0.f, slot_v2 = 0.f;
    int   slot_i1 = 0,   slot_i2 = 0;
    #pragma unroll
    for (int t = 0; t < 16; t++) {
        {
            float bv = v1[0]; int bi = lane;
            #pragma unroll
            for (int i = 1; i < 4; i++)
                if (v1[i] > bv) { bv = v1[i]; bi = lane + 32 * i; }
            #pragma unroll
            for (int off = 16; off > 0; off >>= 1) {
                float ov = __shfl_down_sync(FULL, bv, off);
                int   oi = __shfl_down_sync(FULL, bi, off);
                if (ov > bv || (ov == bv && oi < bi)) { bv = ov; bi = oi; }
            }
            bv = __shfl_sync(FULL, bv, 0);
            bi = __shfl_sync(FULL, bi, 0);
            if (lane == t) { slot_v1 = bv; slot_i1 = bi; }
            int sl = bi >> 5, ol = bi & 31;
            if (lane == ol) {
                if      (sl == 0) v1[0] = -3.4e38f;
                else if (sl == 1) v1[1] = -3.4e38f;
                else if (sl == 2) v1[2] = -3.4e38f;
                else              v1[3] = -3.4e38f;
            }
        }
        {
            float bv = v2[0]; int bi = lane;
            #pragma unroll
            for (int i = 1; i < 4; i++)
                if (v2[i] > bv) { bv = v2[i]; bi = lane + 32 * i; }
            #pragma unroll
            for (int off = 16; off > 0; off >>= 1) {
                float ov = __shfl_down_sync(FULL, bv, off);
                int   oi = __shfl_down_sync(FULL, bi, off);
                if (ov > bv || (ov == bv && oi < bi)) { bv = ov; bi = oi; }
            }
            bv = __shfl_sync(FULL, bv, 0);
            bi = __shfl_sync(FULL, bi, 0);
            if (lane == t) { slot_v2 = bv; slot_i2 = bi; }
            int sl = bi >> 5, ol = bi & 31;
            if (lane == ol) {
                if      (sl == 0) v2[0] = -3.4e38f;
                else if (sl == 1) v2[1] = -3.4e38f;
                else if (sl == 2) v2[2] = -3.4e38f;
                else              v2[3] = -3.4e38f;
            }
        }
    }

    float cv[8];
    #pragma unroll
    for (int j = 0; j < 8; j++) {
        int c = lane + 32 * j;
        float a = __shfl_sync(FULL, slot_v1, c >> 4);
        float b = __shfl_sync(FULL, slot_v2, c & 15);
        cv[j] = a + b;
    }

    float sel_v = -3.4e38f; int sel_c = 0;
    #pragma unroll
    for (int t = 0; t < 8; t++) {
        float bv = cv[0]; int bc = lane;
        #pragma unroll
        for (int j = 1; j < 8; j++)
            if (cv[j] > bv) { bv = cv[j]; bc = lane + 32 * j; }
        #pragma unroll
        for (int off = 16; off > 0; off >>= 1) {
            float ov = __shfl_down_sync(FULL, bv, off);
            int   oc = __shfl_down_sync(FULL, bc, off);
            if (ov > bv || (ov == bv && oc < bc)) { bv = ov; bc = oc; }
        }
        bv = __shfl_sync(FULL, bv, 0);
        bc = __shfl_sync(FULL, bc, 0);
        if (lane == t) { sel_v = bv; sel_c = bc; }
        int sl = bc >> 5, ol = bc & 31;
        if (lane == ol) {
            switch (sl) {
                case 0: cv[0] = -3.4e38f; break;
                case 1: cv[1] = -3.4e38f; break;
                case 2: cv[2] = -3.4e38f; break;
                case 3: cv[3] = -3.4e38f; break;
                case 4: cv[4] = -3.4e38f; break;
                case 5: cv[5] = -3.4e38f; break;
                case 6: cv[6] = -3.4e38f; break;
                default: cv[7] = -3.4e38f; break;
            }
        }
    }

    float mv = (lane < 8) ? sel_v : -3.4e38f;
    #pragma unroll
    for (int off = 4; off > 0; off >>= 1)
        mv = fmaxf(mv, __shfl_xor_sync(FULL, mv, off));
    float ev = (lane < 8) ? expf(sel_v - mv) : 0.0f;
    float sum = ev;
    #pragma unroll
    for (int off = 4; off > 0; off >>= 1)
        sum += __shfl_xor_sync(FULL, sum, off);
    float p = ev / sum;

    int i1 = __shfl_sync(FULL, slot_i1, sel_c >> 4);
    int i2 = __shfl_sync(FULL, slot_i2, sel_c & 15);
    if (lane < 8) {
        g_probs[(size_t)gw * 8 + lane] = p;
        g_eidx [(size_t)gw * 8 + lane] = i1 * NSUB + i2;
    }
}

// ---------------- expert gather + dot + gelu + weighted accumulate ----------------
__global__ void __launch_bounds__(256) gather_kernel() {
    const unsigned FULL = 0xffffffffu;
    __shared__ float sx[DH];
    __shared__ float sacc[8][DH];
    int n = blockIdx.x;
    int tid = threadIdx.x;
    int w = tid >> 5, lane = tid & 31;

    sx[tid]       = g_xp[(size_t)n * DH + tid];
    sx[tid + 256] = g_xp[(size_t)n * DH + tid + 256];
    #pragma unroll
    for (int i = 0; i < 16; i++) sacc[w][lane + 32 * i] = 0.0f;
    __syncthreads();

    #pragma unroll
    for (int p = 0; p < 4; p++) {
        int idx = w * 4 + p;
        int e = g_eidx[(size_t)n * 32 + idx];
        float prob = g_probs[(size_t)n * 32 + idx];
        const float* hrow = g_H + (size_t)e * DH;
        float hv[16];
        float dot = 0.0f;
        #pragma unroll
        for (int i = 0; i < 16; i++) {
            hv[i] = hrow[lane + 32 * i];
            dot = fmaf(hv[i], sx[lane + 32 * i], dot);
        }
        #pragma unroll
        for (int off = 16; off > 0; off >>= 1)
            dot += __shfl_down_sync(FULL, dot, off);
        dot = __shfl_sync(FULL, dot, 0);
        float act = gelu_exact(dot) * prob;
        #pragma unroll
        for (int i = 0; i < 16; i++)
            sacc[w][lane + 32 * i] = fmaf(act, hv[i], sacc[w][lane + 32 * i]);
    }
    __syncthreads();

    for (int c = tid; c < DH; c += 256) {
        float s = 0.0f;
        #pragma unroll
        for (int ww = 0; ww < 8; ww++) s += sacc[ww][c];
        g_acc[(size_t)n * DH + c] = s;
    }
}

// ---------------- host launcher ----------------
extern "C" void kernel_launch(void* const* d_in, const int* in_sizes, int n_in,
                              void* d_out, int out_size) {
    (void)in_sizes; (void)n_in; (void)out_size;
    const float* x    = (const float*)d_in[0];
    const float* Wq   = (const float*)d_in[1];
    const float* bq   = (const float*)d_in[2];
    const float* gam  = (const float*)d_in[3];
    const float* bet  = (const float*)d_in[4];
    const float* sk1  = (const float*)d_in[5];
    const float* sk2  = (const float*)d_in[6];
    const float* lat  = (const float*)d_in[7];
    const float* W1   = (const float*)d_in[8];
    const float* W2   = (const float*)d_in[9];
    float* out = (float*)d_out;

    float *q, *sk1a, *sk2a, *bs1, *bs2, *s1, *s2, *H, *xp, *acc;
    cudaGetSymbolAddress((void**)&q,    g_q);
    cudaGetSymbolAddress((void**)&sk1a, g_sk1a);
    cudaGetSymbolAddress((void**)&sk2a, g_sk2a);
    cudaGetSymbolAddress((void**)&bs1,  g_bs1);
    cudaGetSymbolAddress((void**)&bs2,  g_bs2);
    cudaGetSymbolAddress((void**)&s1,   g_s1);
    cudaGetSymbolAddress((void**)&s2,   g_s2);
    cudaGetSymbolAddress((void**)&H,    g_H);
    cudaGetSymbolAddress((void**)&xp,   g_xp);
    cudaGetSymbolAddress((void**)&acc,  g_acc);

    // 1. zero BN accumulators
    zero_stats_kernel<<<1, 1024>>>();

    // 2. q = x @ Wq^T + bq   [8192,1024] x [1024,1024]^T
    sgemm128<<<dim3(8, 64), 256>>>(x, Wq, q, bq,
                                   1024, 1024, 1024, 1024,
                                   0, 0, 0, 0, 1, 1, 1.0f);

    // 3-5. BN stats, fold into affine, fold affine into score weights
    bn_reduce_kernel<<<128, 256>>>();
    bn_finalize_kernel<<<1, 1024>>>(gam, bet);
    fold_sk_kernel<<<512, 128>>>(sk1, sk2);

    // 6-7. s1, s2 = q_half @ (sk*a)^T + bias  (batched over heads via z)
    sgemm128<<<dim3(1, 64, 4), 256>>>(q, sk1a, s1, bs1,
                                      128, 1024, 128, 512,
                                      256, 128 * 128, 128, 128, 1, 1, 1.0f);
    sgemm128<<<dim3(1, 64, 4), 256>>>(q + 128, sk2a, s2, bs2,
                                      128, 1024, 128, 512,
                                      256, 128 * 128, 128, 128, 1, 1, 1.0f);

    // 8. top-16 x top-16 -> top-8, softmax, expert indices
    topk_kernel<<<4096, 256>>>();

    // 9. H = gelu(latents @ W1)   [16384,256] x [256,512]
    sgemm128<<<dim3(4, 128), 256>>>(lat, W1, H, nullptr,
                                    256, 256, 512, 512,
                                    0, 0, 0, 0, 0, 2, 1.0f);

    // 10. x_proj = x @ W2[:, :1024]^T   [8192,1024] x [512,1024(ld2048)]^T
    sgemm128<<<dim3(4, 64), 256>>>(x, W2, xp, nullptr,
                                   1024, 1024, 2048, 512,
                                   0, 0, 0, 0, 1, 0, 1.0f);

    // 11. gather experts, act = gelu(<hg, x_proj>)*prob, acc = sum act*hg
    gather_kernel<<<NTOK, 256>>>();

    // 12. out = acc @ Wv / NUM_HEADS   [8192,512] x [512,1024(ld2048)]
    sgemm128<<<dim3(8, 64), 256>>>(acc, W2 + 1024, out, nullptr,
                                   512, 512, 2048, 1024,
                                   0, 0, 0, 0, 0, 0, 0.25f);
}